// round 1
// baseline (speedup 1.0000x reference)
#include <cuda_runtime.h>
#include <math.h>

#define NLOC 1940
#define NPRI 8732
#define BATCH 16
#define TOPK 10
#define NOBJ (BATCH*TOPK)
#define DS 64          // decoded image size
#define IMG 300
#define ZWHAT 64

// scratch (device globals; no allocation allowed)
__device__ float g_decoded[NOBJ * 3 * DS * DS];   // ~7.9 MB
__device__ int   g_order[BATCH * TOPK];

// prior index -> location index (closed form of _recon_indices)
__device__ __forceinline__ int prior_to_loc(int i) {
    if (i < 5776) return i >> 2;                       // 38x38, 4/loc
    if (i < 7942) return 1444 + (i - 5776) / 6;        // 19x19, 6/loc
    if (i < 8542) return 1805 + (i - 7942) / 6;        // 10x10, 6/loc
    if (i < 8692) return 1905 + (i - 8542) / 6;        // 5x5,   6/loc
    if (i < 8728) return 1930 + ((i - 8692) >> 2);     // 3x3,   4/loc
    return 1939;                                        // 1x1
}

// ---------------------------------------------------------------------------
// Kernel 1: per-batch top-10 of gathered depths, stable tie-break by index.
// ---------------------------------------------------------------------------
__global__ void __launch_bounds__(256) topk_kernel(const float* __restrict__ z_depth) {
    const int b = blockIdx.x;
    const int tid = threadIdx.x;
    __shared__ float sv[256];
    __shared__ int   si[256];
    __shared__ float s_tv;
    __shared__ int   s_ti;

    float tv = 0.0f; int ti = -1;   // previously selected (value, index)
    for (int j = 0; j < TOPK; j++) {
        float bestv = -INFINITY;
        int   besti = 0x7fffffff;
        for (int i = tid; i < NPRI; i += 256) {
            float v = z_depth[b * NLOC + prior_to_loc(i)];
            bool elig = (j == 0) || (v < tv) || (v == tv && i > ti);
            if (elig && (v > bestv || (v == bestv && i < besti))) {
                bestv = v; besti = i;
            }
        }
        sv[tid] = bestv; si[tid] = besti;
        __syncthreads();
        for (int s = 128; s > 0; s >>= 1) {
            if (tid < s) {
                if (sv[tid + s] > sv[tid] ||
                    (sv[tid + s] == sv[tid] && si[tid + s] < si[tid])) {
                    sv[tid] = sv[tid + s]; si[tid] = si[tid + s];
                }
            }
            __syncthreads();
        }
        if (tid == 0) {
            g_order[b * TOPK + j] = si[0];
            s_tv = sv[0]; s_ti = si[0];
        }
        __syncthreads();
        tv = s_tv; ti = s_ti;
        __syncthreads();
    }
}

// ---------------------------------------------------------------------------
// Kernel 2: decode 160 objects. One block per object; activations in smem.
// deconv2x2 stride 2: out[o,2y+a,2x+b] = bias[o] + sum_c in[c,y,x]*W[c,o,a,b]
// ---------------------------------------------------------------------------
__device__ __forceinline__ void dlayer(const float* __restrict__ in, float* out,
                                       int ci, int co, int h, int w,
                                       const float* __restrict__ Wt,
                                       const float* __restrict__ bias,
                                       bool is_sigmoid) {
    const int hw = h * w;
    const int total = co * hw;
    const int w2 = 2 * w;
    const float4* __restrict__ W4 = reinterpret_cast<const float4*>(Wt);
    for (int t = threadIdx.x; t < total; t += blockDim.x) {
        const int o = t % co;          // consecutive threads -> coalesced W float4
        const int pix = t / co;        // same pixel across warp -> smem broadcast
        const int y = pix / w, x = pix % w;
        const float* ip = in + y * w + x;
        const float bo = __ldg(bias + o);
        float a0 = bo, a1 = bo, a2 = bo, a3 = bo;
        #pragma unroll 4
        for (int c = 0; c < ci; c++) {
            const float iv = ip[c * hw];
            const float4 wv = __ldg(W4 + c * co + o);
            a0 += iv * wv.x; a1 += iv * wv.y; a2 += iv * wv.z; a3 += iv * wv.w;
        }
        if (is_sigmoid) {
            a0 = 1.0f / (1.0f + expf(-a0));
            a1 = 1.0f / (1.0f + expf(-a1));
            a2 = 1.0f / (1.0f + expf(-a2));
            a3 = 1.0f / (1.0f + expf(-a3));
        } else {
            a0 = fmaxf(a0, 0.0f); a1 = fmaxf(a1, 0.0f);
            a2 = fmaxf(a2, 0.0f); a3 = fmaxf(a3, 0.0f);
        }
        float* op = out + (o * 2 * h + 2 * y) * w2 + 2 * x;
        op[0]     = a0;           // (a=0,b=0)
        op[1]     = a1;           // (a=0,b=1)
        op[w2]    = a2;           // (a=1,b=0)
        op[w2 + 1] = a3;          // (a=1,b=1)
    }
}

__global__ void __launch_bounds__(256) decode_kernel(
    const float* __restrict__ z_what,
    const float* __restrict__ W0, const float* __restrict__ b0,
    const float* __restrict__ W1, const float* __restrict__ b1,
    const float* __restrict__ W2, const float* __restrict__ b2,
    const float* __restrict__ W3, const float* __restrict__ b3,
    const float* __restrict__ W4, const float* __restrict__ b4,
    const float* __restrict__ W5, const float* __restrict__ b5)
{
    extern __shared__ float sm[];
    float* bufA = sm;           // needs up to 8192 floats
    float* bufB = sm + 8192;    // needs up to 16384 floats

    const int m = blockIdx.x;          // object id
    const int b = m / TOPK;

    // gather z_what for this object
    const int ord = g_order[m];
    const int loc = prior_to_loc(ord);
    const float* src = z_what + (size_t)(b * NLOC + loc) * ZWHAT;
    for (int i = threadIdx.x; i < ZWHAT; i += blockDim.x) bufA[i] = src[i];
    __syncthreads();

    dlayer(bufA, bufB, 64, 256, 1, 1, W0, b0, false);  __syncthreads(); // 256x2x2
    dlayer(bufB, bufA, 256, 128, 2, 2, W1, b1, false); __syncthreads(); // 128x4x4
    dlayer(bufA, bufB, 128, 64, 4, 4, W2, b2, false);  __syncthreads(); // 64x8x8
    dlayer(bufB, bufA, 64, 32, 8, 8, W3, b3, false);   __syncthreads(); // 32x16x16
    dlayer(bufA, bufB, 32, 16, 16, 16, W4, b4, false); __syncthreads(); // 16x32x32
    // last layer writes straight to global decoded buffer
    dlayer(bufB, g_decoded + (size_t)m * 3 * DS * DS, 16, 3, 32, 32, W5, b5, true);
}

// ---------------------------------------------------------------------------
// Kernel 3: fused STN + depth-ordered first-nonzero compositing.
// ---------------------------------------------------------------------------
__global__ void __launch_bounds__(256) composite_kernel(
    const float* __restrict__ z_where,
    const int*   __restrict__ z_present,
    float* __restrict__ out)
{
    const int b = blockIdx.y;
    __shared__ float s_cx[TOPK], s_cy[TOPK], s_w[TOPK], s_h[TOPK];
    __shared__ int   s_p[TOPK];
    if (threadIdx.x < TOPK) {
        const int ord = g_order[b * TOPK + threadIdx.x];
        const float* zw = z_where + (size_t)(b * NPRI + ord) * 4;
        s_cx[threadIdx.x] = zw[0];
        s_cy[threadIdx.x] = zw[1];
        s_w[threadIdx.x]  = zw[2];
        s_h[threadIdx.x]  = zw[3];
        s_p[threadIdx.x]  = z_present[b * NPRI + ord];
    }
    __syncthreads();

    const int p = blockIdx.x * blockDim.x + threadIdx.x;
    if (p >= IMG * IMG) return;
    const int y = p / IMG, x = p % IMG;
    const float xo = (2.0f * (float)x + 1.0f) / (float)IMG - 1.0f;
    const float yo = (2.0f * (float)y + 1.0f) / (float)IMG - 1.0f;

    float r0 = 0.0f, r1 = 0.0f, r2 = 0.0f;
    int done = 0;

    for (int k = 0; k < TOPK; k++) {
        if (s_p[k] != 1) continue;
        const float u = (xo - (2.0f * s_cx[k] - 1.0f)) / (s_w[k] + 1e-6f);
        const float v = (yo - (2.0f * s_cy[k] - 1.0f)) / (s_h[k] + 1e-6f);
        const float ix = ((u + 1.0f) * (float)DS - 1.0f) * 0.5f;
        const float iy = ((v + 1.0f) * (float)DS - 1.0f) * 0.5f;
        const float ix0f = floorf(ix), iy0f = floorf(iy);
        if (!(ix0f >= -1.0f && ix0f <= 63.0f && iy0f >= -1.0f && iy0f <= 63.0f))
            continue;   // sample exactly zero -> never "first"
        const float wx1 = ix - ix0f, wy1 = iy - iy0f;
        const float wx0 = 1.0f - wx1, wy0 = 1.0f - wy1;
        const int ix0 = (int)ix0f, iy0 = (int)iy0f;
        const bool vx0 = (ix0 >= 0), vx1 = (ix0 <= 62);
        const bool vy0 = (iy0 >= 0), vy1 = (iy0 <= 62);
        const float w00 = (vy0 && vx0) ? wy0 * wx0 : 0.0f;
        const float w01 = (vy0 && vx1) ? wy0 * wx1 : 0.0f;
        const float w10 = (vy1 && vx0) ? wy1 * wx0 : 0.0f;
        const float w11 = (vy1 && vx1) ? wy1 * wx1 : 0.0f;
        const int x0c = max(ix0, 0),     x1c = min(ix0 + 1, DS - 1);
        const int y0c = max(iy0, 0),     y1c = min(iy0 + 1, DS - 1);
        const int i00 = y0c * DS + x0c, i01 = y0c * DS + x1c;
        const int i10 = y1c * DS + x0c, i11 = y1c * DS + x1c;
        const float* base = g_decoded + (size_t)(b * TOPK + k) * 3 * DS * DS;

        #pragma unroll
        for (int c = 0; c < 3; c++) {
            const float* im = base + c * DS * DS;
            const float s = __ldg(im + i00) * w00 + __ldg(im + i01) * w01 +
                            __ldg(im + i10) * w10 + __ldg(im + i11) * w11;
            if (!(done & (1 << c)) && s != 0.0f) {
                if (c == 0) r0 = s; else if (c == 1) r1 = s; else r2 = s;
                done |= (1 << c);
            }
        }
        if (done == 7) break;
    }

    const size_t pix = (size_t)y * IMG + x;
    out[((size_t)(b * 3 + 0) * IMG * IMG) + pix] = r0;
    out[((size_t)(b * 3 + 1) * IMG * IMG) + pix] = r1;
    out[((size_t)(b * 3 + 2) * IMG * IMG) + pix] = r2;
}

// ---------------------------------------------------------------------------
extern "C" void kernel_launch(void* const* d_in, const int* in_sizes, int n_in,
                              void* d_out, int out_size)
{
    const float* z_what    = (const float*)d_in[0];
    const float* z_where   = (const float*)d_in[1];
    const int*   z_present = (const int*)  d_in[2];
    const float* z_depth   = (const float*)d_in[3];
    const float* W0 = (const float*)d_in[4];  const float* b0 = (const float*)d_in[5];
    const float* W1 = (const float*)d_in[6];  const float* b1 = (const float*)d_in[7];
    const float* W2 = (const float*)d_in[8];  const float* b2 = (const float*)d_in[9];
    const float* W3 = (const float*)d_in[10]; const float* b3 = (const float*)d_in[11];
    const float* W4 = (const float*)d_in[12]; const float* b4 = (const float*)d_in[13];
    const float* W5 = (const float*)d_in[14]; const float* b5 = (const float*)d_in[15];
    float* out = (float*)d_out;

    static bool attr_set = false;
    if (!attr_set) {
        cudaFuncSetAttribute(decode_kernel,
                             cudaFuncAttributeMaxDynamicSharedMemorySize,
                             (8192 + 16384) * sizeof(float));
        attr_set = true;
    }

    topk_kernel<<<BATCH, 256>>>(z_depth);

    decode_kernel<<<NOBJ, 256, (8192 + 16384) * sizeof(float)>>>(
        z_what, W0, b0, W1, b1, W2, b2, W3, b3, W4, b4, W5, b5);

    dim3 cgrid((IMG * IMG + 255) / 256, BATCH);
    composite_kernel<<<cgrid, 256>>>(z_where, z_present, out);
}

// round 2
// speedup vs baseline: 1.2028x; 1.2028x over previous
#include <cuda_runtime.h>
#include <math.h>

#define NLOC 1940
#define NPRI 8732
#define BATCH 16
#define TOPK 10
#define NOBJ (BATCH*TOPK)
#define DS 64          // decoded image size
#define IMG 300
#define ZWHAT 64

// scratch (device globals; no allocation allowed)
__device__ float g_decoded[NOBJ * 3 * DS * DS];   // interleaved [obj][pix][c]
__device__ int   g_order[BATCH * TOPK];

// prior index -> location index (closed form of _recon_indices)
__device__ __forceinline__ int prior_to_loc(int i) {
    if (i < 5776) return i >> 2;                       // 38x38, 4/loc
    if (i < 7942) return 1444 + (i - 5776) / 6;        // 19x19, 6/loc
    if (i < 8542) return 1805 + (i - 7942) / 6;        // 10x10, 6/loc
    if (i < 8692) return 1905 + (i - 8542) / 6;        // 5x5,   6/loc
    if (i < 8728) return 1930 + ((i - 8692) >> 2);     // 3x3,   4/loc
    return 1939;                                        // 1x1
}

// location index -> (first prior index, boxes per location)
__device__ __forceinline__ void loc_to_priors(int l, int& start, int& bpl) {
    if (l < 1444)      { start = 4 * l;                bpl = 4; }
    else if (l < 1805) { start = 5776 + 6 * (l - 1444); bpl = 6; }
    else if (l < 1905) { start = 7942 + 6 * (l - 1805); bpl = 6; }
    else if (l < 1930) { start = 8542 + 6 * (l - 1905); bpl = 6; }
    else               { start = 8692 + 4 * (l - 1930); bpl = 4; }
}

// ---------------------------------------------------------------------------
// Kernel 1: per-batch top-3 LOCATIONS by depth (desc, tie: loc asc), then
// expand to the first 10 priors. Exactly matches stable argsort(-zd) because
// each location's priors are contiguous, index-ascending exact ties, and
// prior index is monotone in location index.
// ---------------------------------------------------------------------------
__global__ void __launch_bounds__(128) topk_kernel(const float* __restrict__ z_depth) {
    const int b = blockIdx.x;
    const int tid = threadIdx.x;
    __shared__ float sv[128];
    __shared__ int   si[128];
    __shared__ float s_tv;
    __shared__ int   s_ti;
    __shared__ int   s_rank[3];

    float tv = 0.0f; int ti = -1;   // previously selected (value, loc)
    for (int r = 0; r < 3; r++) {
        float bestv = -INFINITY;
        int   besti = 0x7fffffff;
        for (int l = tid; l < NLOC; l += 128) {
            float v = z_depth[b * NLOC + l];
            bool elig = (r == 0) || (v < tv) || (v == tv && l > ti);
            if (elig && (v > bestv || (v == bestv && l < besti))) {
                bestv = v; besti = l;
            }
        }
        sv[tid] = bestv; si[tid] = besti;
        __syncthreads();
        for (int s = 64; s > 0; s >>= 1) {
            if (tid < s) {
                if (sv[tid + s] > sv[tid] ||
                    (sv[tid + s] == sv[tid] && si[tid + s] < si[tid])) {
                    sv[tid] = sv[tid + s]; si[tid] = si[tid + s];
                }
            }
            __syncthreads();
        }
        if (tid == 0) {
            s_rank[r] = si[0];
            s_tv = sv[0]; s_ti = si[0];
        }
        __syncthreads();
        tv = s_tv; ti = s_ti;
        __syncthreads();
    }
    if (tid == 0) {
        int cnt = 0;
        #pragma unroll
        for (int r = 0; r < 3 && cnt < TOPK; r++) {
            int start, bpl;
            loc_to_priors(s_rank[r], start, bpl);
            for (int j = 0; j < bpl && cnt < TOPK; j++)
                g_order[b * TOPK + cnt++] = start + j;
        }
    }
}

// ---------------------------------------------------------------------------
// Kernel 2: decode 160 objects. One block per object; activations in smem.
// deconv2x2 stride 2: out[o,2y+a,2x+b] = bias[o] + sum_c in[c,y,x]*W[c,o,a,b]
// ---------------------------------------------------------------------------
template <bool SIGMOID, bool ILEAVE>
__device__ __forceinline__ void dlayer(const float* __restrict__ in, float* out,
                                       int ci, int co, int h, int w,
                                       const float* __restrict__ Wt,
                                       const float* __restrict__ bias) {
    const int hw = h * w;
    const int total = co * hw;
    const int w2 = 2 * w;
    const float4* __restrict__ W4 = reinterpret_cast<const float4*>(Wt);
    for (int t = threadIdx.x; t < total; t += blockDim.x) {
        const int o = t % co;          // consecutive threads -> coalesced W float4
        const int pix = t / co;        // same pixel across warp -> smem broadcast
        const int y = pix / w, x = pix % w;
        const float* ip = in + y * w + x;
        const float bo = __ldg(bias + o);
        float a0 = bo, a1 = bo, a2 = bo, a3 = bo;
        #pragma unroll 4
        for (int c = 0; c < ci; c++) {
            const float iv = ip[c * hw];
            const float4 wv = __ldg(W4 + c * co + o);
            a0 += iv * wv.x; a1 += iv * wv.y; a2 += iv * wv.z; a3 += iv * wv.w;
        }
        if (SIGMOID) {
            a0 = 1.0f / (1.0f + expf(-a0));
            a1 = 1.0f / (1.0f + expf(-a1));
            a2 = 1.0f / (1.0f + expf(-a2));
            a3 = 1.0f / (1.0f + expf(-a3));
        } else {
            a0 = fmaxf(a0, 0.0f); a1 = fmaxf(a1, 0.0f);
            a2 = fmaxf(a2, 0.0f); a3 = fmaxf(a3, 0.0f);
        }
        if (ILEAVE) {
            // channel-interleaved output: out[((2y+a)*w2 + 2x+b)*co + o]
            float* op = out + ((2 * y) * w2 + 2 * x) * co + o;
            op[0]          = a0;
            op[co]         = a1;
            op[w2 * co]    = a2;
            op[w2 * co + co] = a3;
        } else {
            float* op = out + (o * 2 * h + 2 * y) * w2 + 2 * x;
            op[0]      = a0;
            op[1]      = a1;
            op[w2]     = a2;
            op[w2 + 1] = a3;
        }
    }
}

__global__ void __launch_bounds__(256) decode_kernel(
    const float* __restrict__ z_what,
    const float* __restrict__ W0, const float* __restrict__ b0,
    const float* __restrict__ W1, const float* __restrict__ b1,
    const float* __restrict__ W2, const float* __restrict__ b2,
    const float* __restrict__ W3, const float* __restrict__ b3,
    const float* __restrict__ W4, const float* __restrict__ b4,
    const float* __restrict__ W5, const float* __restrict__ b5)
{
    extern __shared__ float sm[];
    float* bufA = sm;           // needs up to 8192 floats
    float* bufB = sm + 8192;    // needs up to 16384 floats

    const int m = blockIdx.x;          // object id
    const int b = m / TOPK;

    // gather z_what for this object
    const int ord = g_order[m];
    const int loc = prior_to_loc(ord);
    const float* src = z_what + (size_t)(b * NLOC + loc) * ZWHAT;
    for (int i = threadIdx.x; i < ZWHAT; i += blockDim.x) bufA[i] = src[i];
    __syncthreads();

    dlayer<false,false>(bufA, bufB, 64, 256, 1, 1, W0, b0);  __syncthreads(); // 256x2x2
    dlayer<false,false>(bufB, bufA, 256, 128, 2, 2, W1, b1); __syncthreads(); // 128x4x4
    dlayer<false,false>(bufA, bufB, 128, 64, 4, 4, W2, b2);  __syncthreads(); // 64x8x8
    dlayer<false,false>(bufB, bufA, 64, 32, 8, 8, W3, b3);   __syncthreads(); // 32x16x16
    dlayer<false,false>(bufA, bufB, 32, 16, 16, 16, W4, b4); __syncthreads(); // 16x32x32
    // last layer writes channel-interleaved straight to global decoded buffer
    dlayer<true,true>(bufB, g_decoded + (size_t)m * 3 * DS * DS, 16, 3, 32, 32, W5, b5);
}

// ---------------------------------------------------------------------------
// Kernel 3: fused STN + depth-ordered first-nonzero compositing.
// g_decoded is channel-interleaved: obj base + (y*DS+x)*3 + c
// ---------------------------------------------------------------------------
__global__ void __launch_bounds__(256) composite_kernel(
    const float* __restrict__ z_where,
    const int*   __restrict__ z_present,
    float* __restrict__ out)
{
    const int b = blockIdx.y;
    __shared__ float s_cx[TOPK], s_cy[TOPK], s_w[TOPK], s_h[TOPK];
    __shared__ int   s_p[TOPK];
    if (threadIdx.x < TOPK) {
        const int ord = g_order[b * TOPK + threadIdx.x];
        const float* zw = z_where + (size_t)(b * NPRI + ord) * 4;
        s_cx[threadIdx.x] = zw[0];
        s_cy[threadIdx.x] = zw[1];
        s_w[threadIdx.x]  = zw[2];
        s_h[threadIdx.x]  = zw[3];
        s_p[threadIdx.x]  = z_present[b * NPRI + ord];
    }
    __syncthreads();

    const int p = blockIdx.x * blockDim.x + threadIdx.x;
    if (p >= IMG * IMG) return;
    const int y = p / IMG, x = p % IMG;
    const float xo = (2.0f * (float)x + 1.0f) / (float)IMG - 1.0f;
    const float yo = (2.0f * (float)y + 1.0f) / (float)IMG - 1.0f;

    float r0 = 0.0f, r1 = 0.0f, r2 = 0.0f;
    int done = 0;

    for (int k = 0; k < TOPK; k++) {
        if (s_p[k] != 1) continue;
        const float u = (xo - (2.0f * s_cx[k] - 1.0f)) / (s_w[k] + 1e-6f);
        const float v = (yo - (2.0f * s_cy[k] - 1.0f)) / (s_h[k] + 1e-6f);
        const float ix = ((u + 1.0f) * (float)DS - 1.0f) * 0.5f;
        const float iy = ((v + 1.0f) * (float)DS - 1.0f) * 0.5f;
        const float ix0f = floorf(ix), iy0f = floorf(iy);
        if (!(ix0f >= -1.0f && ix0f <= 63.0f && iy0f >= -1.0f && iy0f <= 63.0f))
            continue;   // sample exactly zero -> never "first"
        const float wx1 = ix - ix0f, wy1 = iy - iy0f;
        const float wx0 = 1.0f - wx1, wy0 = 1.0f - wy1;
        const int ix0 = (int)ix0f, iy0 = (int)iy0f;
        const bool vx0 = (ix0 >= 0), vx1 = (ix0 <= 62);
        const bool vy0 = (iy0 >= 0), vy1 = (iy0 <= 62);
        const float w00 = (vy0 && vx0) ? wy0 * wx0 : 0.0f;
        const float w01 = (vy0 && vx1) ? wy0 * wx1 : 0.0f;
        const float w10 = (vy1 && vx0) ? wy1 * wx0 : 0.0f;
        const float w11 = (vy1 && vx1) ? wy1 * wx1 : 0.0f;
        const int x0c = max(ix0, 0),     x1c = min(ix0 + 1, DS - 1);
        const int y0c = max(iy0, 0),     y1c = min(iy0 + 1, DS - 1);
        const int i00 = (y0c * DS + x0c) * 3, i01 = (y0c * DS + x1c) * 3;
        const int i10 = (y1c * DS + x0c) * 3, i11 = (y1c * DS + x1c) * 3;
        const float* base = g_decoded + (size_t)(b * TOPK + k) * 3 * DS * DS;

        #pragma unroll
        for (int c = 0; c < 3; c++) {
            const float s = __ldg(base + i00 + c) * w00 + __ldg(base + i01 + c) * w01 +
                            __ldg(base + i10 + c) * w10 + __ldg(base + i11 + c) * w11;
            if (!(done & (1 << c)) && s != 0.0f) {
                if (c == 0) r0 = s; else if (c == 1) r1 = s; else r2 = s;
                done |= (1 << c);
            }
        }
        if (done == 7) break;
    }

    const size_t pix = (size_t)y * IMG + x;
    out[((size_t)(b * 3 + 0) * IMG * IMG) + pix] = r0;
    out[((size_t)(b * 3 + 1) * IMG * IMG) + pix] = r1;
    out[((size_t)(b * 3 + 2) * IMG * IMG) + pix] = r2;
}

// ---------------------------------------------------------------------------
extern "C" void kernel_launch(void* const* d_in, const int* in_sizes, int n_in,
                              void* d_out, int out_size)
{
    const float* z_what    = (const float*)d_in[0];
    const float* z_where   = (const float*)d_in[1];
    const int*   z_present = (const int*)  d_in[2];
    const float* z_depth   = (const float*)d_in[3];
    const float* W0 = (const float*)d_in[4];  const float* b0 = (const float*)d_in[5];
    const float* W1 = (const float*)d_in[6];  const float* b1 = (const float*)d_in[7];
    const float* W2 = (const float*)d_in[8];  const float* b2 = (const float*)d_in[9];
    const float* W3 = (const float*)d_in[10]; const float* b3 = (const float*)d_in[11];
    const float* W4 = (const float*)d_in[12]; const float* b4 = (const float*)d_in[13];
    const float* W5 = (const float*)d_in[14]; const float* b5 = (const float*)d_in[15];
    float* out = (float*)d_out;

    static bool attr_set = false;
    if (!attr_set) {
        cudaFuncSetAttribute(decode_kernel,
                             cudaFuncAttributeMaxDynamicSharedMemorySize,
                             (8192 + 16384) * sizeof(float));
        attr_set = true;
    }

    topk_kernel<<<BATCH, 128>>>(z_depth);

    decode_kernel<<<NOBJ, 256, (8192 + 16384) * sizeof(float)>>>(
        z_what, W0, b0, W1, b1, W2, b2, W3, b3, W4, b4, W5, b5);

    dim3 cgrid((IMG * IMG + 255) / 256, BATCH);
    composite_kernel<<<cgrid, 256>>>(z_where, z_present, out);
}

// round 4
// speedup vs baseline: 1.6054x; 1.3347x over previous
#include <cuda_runtime.h>
#include <math.h>

#define NLOC 1940
#define NPRI 8732
#define BATCH 16
#define TOPK 10
#define NOBJ (BATCH*TOPK)
#define DS 64          // decoded image size
#define IMG 300
#define ZWHAT 64
#define CPAD 4         // padded channel count (3 used + 1 pad) -> 16B/pixel

// scratch (device globals; no allocation allowed)
__device__ float g_decoded[NOBJ * CPAD * DS * DS];   // [obj][pix][4], 10.5 MB
__device__ int   g_order[BATCH * TOPK];

// prior index -> location index (closed form of _recon_indices)
__device__ __forceinline__ int prior_to_loc(int i) {
    if (i < 5776) return i >> 2;                       // 38x38, 4/loc
    if (i < 7942) return 1444 + (i - 5776) / 6;        // 19x19, 6/loc
    if (i < 8542) return 1805 + (i - 7942) / 6;        // 10x10, 6/loc
    if (i < 8692) return 1905 + (i - 8542) / 6;        // 5x5,   6/loc
    if (i < 8728) return 1930 + ((i - 8692) >> 2);     // 3x3,   4/loc
    return 1939;                                        // 1x1
}

// location index -> (first prior index, boxes per location)
__device__ __forceinline__ void loc_to_priors(int l, int& start, int& bpl) {
    if (l < 1444)      { start = 4 * l;                 bpl = 4; }
    else if (l < 1805) { start = 5776 + 6 * (l - 1444); bpl = 6; }
    else if (l < 1905) { start = 7942 + 6 * (l - 1805); bpl = 6; }
    else if (l < 1930) { start = 8542 + 6 * (l - 1905); bpl = 6; }
    else               { start = 8692 + 4 * (l - 1930); bpl = 4; }
}

// (value desc, index asc) comparator
__device__ __forceinline__ bool better(float a, int ia, float b, int ib) {
    return a > b || (a == b && ia < ib);
}
__device__ __forceinline__ void insert3(float v, int i,
                                        float& v0, int& i0,
                                        float& v1, int& i1,
                                        float& v2, int& i2) {
    if (better(v, i, v0, i0)) { v2 = v1; i2 = i1; v1 = v0; i1 = i0; v0 = v; i0 = i; }
    else if (better(v, i, v1, i1)) { v2 = v1; i2 = i1; v1 = v; i1 = i; }
    else if (better(v, i, v2, i2)) { v2 = v; i2 = i; }
}

// ---------------------------------------------------------------------------
// Kernel 1: per-batch top-3 LOCATIONS (single pass + triple-merge reduction),
// then expand to the first 10 priors. Matches stable argsort(-zd) because each
// location's priors are contiguous index-ascending exact ties and prior index
// is monotone in location index (min bpl=4 => top-10 priors come from <=3 locs).
// ---------------------------------------------------------------------------
__global__ void __launch_bounds__(256) topk_kernel(const float* __restrict__ z_depth) {
    const int b = blockIdx.x;
    const int tid = threadIdx.x;
    __shared__ float sv[256][3];
    __shared__ int   si[256][3];

    float v0 = -INFINITY, v1 = -INFINITY, v2 = -INFINITY;
    int   i0 = 0x7fffffff, i1 = 0x7fffffff, i2 = 0x7fffffff;
    for (int l = tid; l < NLOC; l += 256) {
        float v = __ldg(z_depth + b * NLOC + l);
        insert3(v, l, v0, i0, v1, i1, v2, i2);
    }
    sv[tid][0] = v0; sv[tid][1] = v1; sv[tid][2] = v2;
    si[tid][0] = i0; si[tid][1] = i1; si[tid][2] = i2;
    __syncthreads();
    for (int s = 128; s > 0; s >>= 1) {
        if (tid < s) {
            #pragma unroll
            for (int j = 0; j < 3; j++)
                insert3(sv[tid + s][j], si[tid + s][j], v0, i0, v1, i1, v2, i2);
            sv[tid][0] = v0; sv[tid][1] = v1; sv[tid][2] = v2;
            si[tid][0] = i0; si[tid][1] = i1; si[tid][2] = i2;
        }
        __syncthreads();
    }
    if (tid == 0) {
        int cnt = 0;
        int ranks[3] = { i0, i1, i2 };
        #pragma unroll
        for (int r = 0; r < 3 && cnt < TOPK; r++) {
            int start, bpl;
            loc_to_priors(ranks[r], start, bpl);
            for (int j = 0; j < bpl && cnt < TOPK; j++)
                g_order[b * TOPK + cnt++] = start + j;
        }
    }
}

// ---------------------------------------------------------------------------
// Kernel 2: decode 160 objects. One block per object; activations in smem.
// deconv2x2 stride 2: out[o,2y+a,2x+b] = bias[o] + sum_c in[c,y,x]*W[c,o,a,b]
// ---------------------------------------------------------------------------
template <bool SIGMOID, bool ILEAVE>
__device__ __forceinline__ void dlayer(const float* __restrict__ in, float* out,
                                       int ci, int co, int h, int w,
                                       const float* __restrict__ Wt,
                                       const float* __restrict__ bias) {
    const int hw = h * w;
    const int total = co * hw;
    const int w2 = 2 * w;
    const float4* __restrict__ W4 = reinterpret_cast<const float4*>(Wt);
    for (int t = threadIdx.x; t < total; t += blockDim.x) {
        const int o = t % co;          // consecutive threads -> coalesced W float4
        const int pix = t / co;        // same pixel across warp -> smem broadcast
        const int y = pix / w, x = pix % w;
        const float* ip = in + y * w + x;
        const float bo = __ldg(bias + o);
        float a0 = bo, a1 = bo, a2 = bo, a3 = bo;
        #pragma unroll 4
        for (int c = 0; c < ci; c++) {
            const float iv = ip[c * hw];
            const float4 wv = __ldg(W4 + c * co + o);
            a0 += iv * wv.x; a1 += iv * wv.y; a2 += iv * wv.z; a3 += iv * wv.w;
        }
        if (SIGMOID) {
            a0 = 1.0f / (1.0f + expf(-a0));
            a1 = 1.0f / (1.0f + expf(-a1));
            a2 = 1.0f / (1.0f + expf(-a2));
            a3 = 1.0f / (1.0f + expf(-a3));
        } else {
            a0 = fmaxf(a0, 0.0f); a1 = fmaxf(a1, 0.0f);
            a2 = fmaxf(a2, 0.0f); a3 = fmaxf(a3, 0.0f);
        }
        if (ILEAVE) {
            // padded channel-interleaved: out[((2y+a)*w2 + 2x+b)*CPAD + o]
            float* op = out + ((2 * y) * w2 + 2 * x) * CPAD + o;
            op[0]                 = a0;
            op[CPAD]              = a1;
            op[w2 * CPAD]         = a2;
            op[w2 * CPAD + CPAD]  = a3;
        } else {
            float* op = out + (o * 2 * h + 2 * y) * w2 + 2 * x;
            op[0]      = a0;
            op[1]      = a1;
            op[w2]     = a2;
            op[w2 + 1] = a3;
        }
    }
}

__global__ void __launch_bounds__(256, 2) decode_kernel(
    const float* __restrict__ z_what,
    const float* __restrict__ W0, const float* __restrict__ b0,
    const float* __restrict__ W1, const float* __restrict__ b1,
    const float* __restrict__ W2, const float* __restrict__ b2,
    const float* __restrict__ W3, const float* __restrict__ b3,
    const float* __restrict__ W4, const float* __restrict__ b4,
    const float* __restrict__ W5, const float* __restrict__ b5)
{
    extern __shared__ float sm[];
    float* bufA = sm;           // needs up to 8192 floats
    float* bufB = sm + 8192;    // needs up to 16384 floats

    const int m = blockIdx.x;          // object id
    const int b = m / TOPK;

    // gather z_what for this object
    const int ord = g_order[m];
    const int loc = prior_to_loc(ord);
    const float* src = z_what + (size_t)(b * NLOC + loc) * ZWHAT;
    for (int i = threadIdx.x; i < ZWHAT; i += blockDim.x) bufA[i] = src[i];
    __syncthreads();

    dlayer<false,false>(bufA, bufB, 64, 256, 1, 1, W0, b0);  __syncthreads(); // 256x2x2
    dlayer<false,false>(bufB, bufA, 256, 128, 2, 2, W1, b1); __syncthreads(); // 128x4x4
    dlayer<false,false>(bufA, bufB, 128, 64, 4, 4, W2, b2);  __syncthreads(); // 64x8x8
    dlayer<false,false>(bufB, bufA, 64, 32, 8, 8, W3, b3);   __syncthreads(); // 32x16x16
    dlayer<false,false>(bufA, bufB, 32, 16, 16, 16, W4, b4); __syncthreads(); // 16x32x32
    // last layer writes padded channel-interleaved straight to global
    dlayer<true,true>(bufB, g_decoded + (size_t)m * CPAD * DS * DS, 16, 3, 32, 32, W5, b5);
}

// ---------------------------------------------------------------------------
// Kernel 3: fused STN + depth-ordered first-nonzero compositing.
// g_decoded is padded interleaved: one float4 per texel (xyz = RGB).
// Per-object affine hoisted to shared: ix = fma(x, sx, ox), iy = fma(y, sy, oy)
//   ix = ((u+1)*DS-1)/2 = u*32 + 31.5,  u = (xo - (2cx-1))/w, xo = (2x+1)/IMG - 1
//   => sx = (32/w)*(2/IMG)
//      ox = 31.5 + (32/w)*((1/IMG - 1) - (2cx - 1))
// ---------------------------------------------------------------------------
__global__ void __launch_bounds__(256) composite_kernel(
    const float* __restrict__ z_where,
    const int*   __restrict__ z_present,
    float* __restrict__ out)
{
    const int b = blockIdx.y;
    __shared__ float s_sx[TOPK], s_ox[TOPK], s_sy[TOPK], s_oy[TOPK];
    __shared__ int   s_p[TOPK];
    if (threadIdx.x < TOPK) {
        const int ord = g_order[b * TOPK + threadIdx.x];
        const float* zw = z_where + (size_t)(b * NPRI + ord) * 4;
        const float cx = zw[0], cy = zw[1];
        const float w = zw[2] + 1e-6f, h = zw[3] + 1e-6f;
        const float half = (float)DS * 0.5f;   // 32
        const float xsn = half / w;
        const float ysn = half / h;
        s_sx[threadIdx.x] = xsn * (2.0f / (float)IMG);
        s_ox[threadIdx.x] = half - 0.5f
                            + xsn * ((1.0f / (float)IMG - 1.0f) - (2.0f * cx - 1.0f));
        s_sy[threadIdx.x] = ysn * (2.0f / (float)IMG);
        s_oy[threadIdx.x] = half - 0.5f
                            + ysn * ((1.0f / (float)IMG - 1.0f) - (2.0f * cy - 1.0f));
        s_p[threadIdx.x]  = z_present[b * NPRI + ord];
    }
    __syncthreads();

    const int p = blockIdx.x * blockDim.x + threadIdx.x;
    if (p >= IMG * IMG) return;
    const int y = p / IMG, x = p % IMG;
    const float fx = (float)x, fy = (float)y;

    float r0 = 0.0f, r1 = 0.0f, r2 = 0.0f;
    int done = 0;

    for (int k = 0; k < TOPK; k++) {
        if (s_p[k] != 1) continue;
        const float ix = fmaf(fx, s_sx[k], s_ox[k]);
        const float iy = fmaf(fy, s_sy[k], s_oy[k]);
        const float ix0f = floorf(ix), iy0f = floorf(iy);
        if (!(ix0f >= -1.0f && ix0f <= 63.0f && iy0f >= -1.0f && iy0f <= 63.0f))
            continue;   // sample exactly zero -> never "first"
        const float wx1 = ix - ix0f, wy1 = iy - iy0f;
        const float wx0 = 1.0f - wx1, wy0 = 1.0f - wy1;
        const int ix0 = (int)ix0f, iy0 = (int)iy0f;
        const bool vx0 = (ix0 >= 0), vx1 = (ix0 <= 62);
        const bool vy0 = (iy0 >= 0), vy1 = (iy0 <= 62);
        const float w00 = (vy0 && vx0) ? wy0 * wx0 : 0.0f;
        const float w01 = (vy0 && vx1) ? wy0 * wx1 : 0.0f;
        const float w10 = (vy1 && vx0) ? wy1 * wx0 : 0.0f;
        const float w11 = (vy1 && vx1) ? wy1 * wx1 : 0.0f;
        const int x0c = max(ix0, 0),     x1c = min(ix0 + 1, DS - 1);
        const int y0c = max(iy0, 0),     y1c = min(iy0 + 1, DS - 1);
        const int i00 = y0c * DS + x0c, i01 = y0c * DS + x1c;
        const int i10 = y1c * DS + x0c, i11 = y1c * DS + x1c;
        const float4* __restrict__ base = reinterpret_cast<const float4*>(g_decoded)
                                          + (size_t)(b * TOPK + k) * DS * DS;
        const float4 t00 = __ldg(base + i00);
        const float4 t01 = __ldg(base + i01);
        const float4 t10 = __ldg(base + i10);
        const float4 t11 = __ldg(base + i11);

        const float s0 = t00.x * w00 + t01.x * w01 + t10.x * w10 + t11.x * w11;
        const float s1 = t00.y * w00 + t01.y * w01 + t10.y * w10 + t11.y * w11;
        const float s2 = t00.z * w00 + t01.z * w01 + t10.z * w10 + t11.z * w11;

        if (!(done & 1) && s0 != 0.0f) { r0 = s0; done |= 1; }
        if (!(done & 2) && s1 != 0.0f) { r1 = s1; done |= 2; }
        if (!(done & 4) && s2 != 0.0f) { r2 = s2; done |= 4; }
        if (done == 7) break;
    }

    const size_t pix = (size_t)y * IMG + x;
    out[((size_t)(b * 3 + 0) * IMG * IMG) + pix] = r0;
    out[((size_t)(b * 3 + 1) * IMG * IMG) + pix] = r1;
    out[((size_t)(b * 3 + 2) * IMG * IMG) + pix] = r2;
}

// ---------------------------------------------------------------------------
extern "C" void kernel_launch(void* const* d_in, const int* in_sizes, int n_in,
                              void* d_out, int out_size)
{
    const float* z_what    = (const float*)d_in[0];
    const float* z_where   = (const float*)d_in[1];
    const int*   z_present = (const int*)  d_in[2];
    const float* z_depth   = (const float*)d_in[3];
    const float* W0 = (const float*)d_in[4];  const float* b0 = (const float*)d_in[5];
    const float* W1 = (const float*)d_in[6];  const float* b1 = (const float*)d_in[7];
    const float* W2 = (const float*)d_in[8];  const float* b2 = (const float*)d_in[9];
    const float* W3 = (const float*)d_in[10]; const float* b3 = (const float*)d_in[11];
    const float* W4 = (const float*)d_in[12]; const float* b4 = (const float*)d_in[13];
    const float* W5 = (const float*)d_in[14]; const float* b5 = (const float*)d_in[15];
    float* out = (float*)d_out;

    static bool attr_set = false;
    if (!attr_set) {
        cudaFuncSetAttribute(decode_kernel,
                             cudaFuncAttributeMaxDynamicSharedMemorySize,
                             (8192 + 16384) * sizeof(float));
        attr_set = true;
    }

    topk_kernel<<<BATCH, 256>>>(z_depth);

    decode_kernel<<<NOBJ, 256, (8192 + 16384) * sizeof(float)>>>(
        z_what, W0, b0, W1, b1, W2, b2, W3, b3, W4, b4, W5, b5);

    dim3 cgrid((IMG * IMG + 255) / 256, BATCH);
    composite_kernel<<<cgrid, 256>>>(z_where, z_present, out);
}

// round 5
// speedup vs baseline: 1.6799x; 1.0464x over previous
#include <cuda_runtime.h>
#include <math.h>

#define NLOC 1940
#define NPRI 8732
#define BATCH 16
#define TOPK 10
#define NOBJ (BATCH*TOPK)
#define DS 64          // decoded image size
#define IMG 300
#define ZWHAT 64
#define CPAD 4         // padded channel count (3 used + 1 pad) -> 16B/pixel
#define TILE 16        // composite tile edge
#define NTX ((IMG + TILE - 1) / TILE)   // 19

// scratch (device globals; no allocation allowed)
__device__ float g_decoded[NOBJ * CPAD * DS * DS];   // [obj][pix][4], 10.5 MB
__device__ int   g_order[BATCH * TOPK];

// prior index -> location index (closed form of _recon_indices)
__device__ __forceinline__ int prior_to_loc(int i) {
    if (i < 5776) return i >> 2;                       // 38x38, 4/loc
    if (i < 7942) return 1444 + (i - 5776) / 6;        // 19x19, 6/loc
    if (i < 8542) return 1805 + (i - 7942) / 6;        // 10x10, 6/loc
    if (i < 8692) return 1905 + (i - 8542) / 6;        // 5x5,   6/loc
    if (i < 8728) return 1930 + ((i - 8692) >> 2);     // 3x3,   4/loc
    return 1939;                                        // 1x1
}

// location index -> (first prior index, boxes per location)
__device__ __forceinline__ void loc_to_priors(int l, int& start, int& bpl) {
    if (l < 1444)      { start = 4 * l;                 bpl = 4; }
    else if (l < 1805) { start = 5776 + 6 * (l - 1444); bpl = 6; }
    else if (l < 1905) { start = 7942 + 6 * (l - 1805); bpl = 6; }
    else if (l < 1930) { start = 8542 + 6 * (l - 1905); bpl = 6; }
    else               { start = 8692 + 4 * (l - 1930); bpl = 4; }
}

// (value desc, index asc) comparator
__device__ __forceinline__ bool better(float a, int ia, float b, int ib) {
    return a > b || (a == b && ia < ib);
}
__device__ __forceinline__ void insert3(float v, int i,
                                        float& v0, int& i0,
                                        float& v1, int& i1,
                                        float& v2, int& i2) {
    if (better(v, i, v0, i0)) { v2 = v1; i2 = i1; v1 = v0; i1 = i0; v0 = v; i0 = i; }
    else if (better(v, i, v1, i1)) { v2 = v1; i2 = i1; v1 = v; i1 = i; }
    else if (better(v, i, v2, i2)) { v2 = v; i2 = i; }
}

// block-redundant top-3 locations of batch b; returns prior index of rank j.
// scratch must hold 256*6 floats. Matches stable argsort(-zd) (ties are
// contiguous index-ascending priors; prior index monotone in location index;
// min bpl=4 => top-10 priors always come from the top-3 locations).
__device__ __forceinline__ int block_topk(const float* __restrict__ z_depth,
                                          int b, int j, float* scratch) {
    const int tid = threadIdx.x;
    float (*sv)[3] = (float(*)[3])scratch;
    int   (*si)[3] = (int(*)[3])(scratch + 256 * 3);

    float v0 = -INFINITY, v1 = -INFINITY, v2 = -INFINITY;
    int   i0 = 0x7fffffff, i1 = 0x7fffffff, i2 = 0x7fffffff;
    const float4* __restrict__ zd4 =
        reinterpret_cast<const float4*>(z_depth + b * NLOC);
    for (int i = tid; i < NLOC / 4; i += 256) {
        const float4 v = __ldg(zd4 + i);
        insert3(v.x, 4 * i + 0, v0, i0, v1, i1, v2, i2);
        insert3(v.y, 4 * i + 1, v0, i0, v1, i1, v2, i2);
        insert3(v.z, 4 * i + 2, v0, i0, v1, i1, v2, i2);
        insert3(v.w, 4 * i + 3, v0, i0, v1, i1, v2, i2);
    }
    sv[tid][0] = v0; sv[tid][1] = v1; sv[tid][2] = v2;
    si[tid][0] = i0; si[tid][1] = i1; si[tid][2] = i2;
    __syncthreads();
    for (int s = 128; s > 0; s >>= 1) {
        if (tid < s) {
            #pragma unroll
            for (int q = 0; q < 3; q++)
                insert3(sv[tid + s][q], si[tid + s][q], v0, i0, v1, i1, v2, i2);
            sv[tid][0] = v0; sv[tid][1] = v1; sv[tid][2] = v2;
            si[tid][0] = i0; si[tid][1] = i1; si[tid][2] = i2;
        }
        __syncthreads();
    }
    // thread 0 holds global top-3 in (v0..v2, i0..i2); expand to prior j
    __shared__ int s_ord;
    if (tid == 0) {
        int ranks[3] = { i0, i1, i2 };
        int ord = -1, cnt = 0;
        #pragma unroll
        for (int r = 0; r < 3; r++) {
            int start, bpl;
            loc_to_priors(ranks[r], start, bpl);
            if (ord < 0 && j < cnt + bpl) ord = start + (j - cnt);
            cnt += bpl;
        }
        s_ord = ord;
    }
    __syncthreads();
    return s_ord;
}

// ---------------------------------------------------------------------------
// Kernel 1: decode 160 objects. One block per object; activations in smem.
// Each block redundantly computes its batch's top-3 (removes topk kernel)
// and publishes g_order[m] for the composite kernel.
// deconv2x2 stride 2: out[o,2y+a,2x+b] = bias[o] + sum_c in[c,y,x]*W[c,o,a,b]
// ---------------------------------------------------------------------------
template <bool SIGMOID, bool ILEAVE>
__device__ __forceinline__ void dlayer(const float* __restrict__ in, float* out,
                                       int ci, int co, int h, int w,
                                       const float* __restrict__ Wt,
                                       const float* __restrict__ bias) {
    const int hw = h * w;
    const int total = co * hw;
    const int w2 = 2 * w;
    const float4* __restrict__ W4 = reinterpret_cast<const float4*>(Wt);
    for (int t = threadIdx.x; t < total; t += blockDim.x) {
        const int o = t % co;          // consecutive threads -> coalesced W float4
        const int pix = t / co;        // same pixel across warp -> smem broadcast
        const int y = pix / w, x = pix % w;
        const float* ip = in + y * w + x;
        const float bo = __ldg(bias + o);
        float a0 = bo, a1 = bo, a2 = bo, a3 = bo;
        #pragma unroll 4
        for (int c = 0; c < ci; c++) {
            const float iv = ip[c * hw];
            const float4 wv = __ldg(W4 + c * co + o);
            a0 += iv * wv.x; a1 += iv * wv.y; a2 += iv * wv.z; a3 += iv * wv.w;
        }
        if (SIGMOID) {
            a0 = 1.0f / (1.0f + expf(-a0));
            a1 = 1.0f / (1.0f + expf(-a1));
            a2 = 1.0f / (1.0f + expf(-a2));
            a3 = 1.0f / (1.0f + expf(-a3));
        } else {
            a0 = fmaxf(a0, 0.0f); a1 = fmaxf(a1, 0.0f);
            a2 = fmaxf(a2, 0.0f); a3 = fmaxf(a3, 0.0f);
        }
        if (ILEAVE) {
            float* op = out + ((2 * y) * w2 + 2 * x) * CPAD + o;
            op[0]                 = a0;
            op[CPAD]              = a1;
            op[w2 * CPAD]         = a2;
            op[w2 * CPAD + CPAD]  = a3;
        } else {
            float* op = out + (o * 2 * h + 2 * y) * w2 + 2 * x;
            op[0]      = a0;
            op[1]      = a1;
            op[w2]     = a2;
            op[w2 + 1] = a3;
        }
    }
}

__global__ void __launch_bounds__(256, 2) decode_kernel(
    const float* __restrict__ z_depth,
    const float* __restrict__ z_what,
    const float* __restrict__ W0, const float* __restrict__ b0,
    const float* __restrict__ W1, const float* __restrict__ b1,
    const float* __restrict__ W2, const float* __restrict__ b2,
    const float* __restrict__ W3, const float* __restrict__ b3,
    const float* __restrict__ W4, const float* __restrict__ b4,
    const float* __restrict__ W5, const float* __restrict__ b5)
{
    extern __shared__ float sm[];
    float* bufA = sm;           // needs up to 8192 floats
    float* bufB = sm + 8192;    // needs up to 16384 floats

    const int m = blockIdx.x;          // object id
    const int b = m / TOPK;
    const int j = m % TOPK;

    // redundant per-block top-3 (uses bufB as scratch, before first use)
    const int ord = block_topk(z_depth, b, j, bufB);
    if (threadIdx.x == 0) g_order[m] = ord;   // publish for composite

    // gather z_what for this object
    const int loc = prior_to_loc(ord);
    const float* src = z_what + (size_t)(b * NLOC + loc) * ZWHAT;
    if (threadIdx.x < ZWHAT) bufA[threadIdx.x] = src[threadIdx.x];
    __syncthreads();

    dlayer<false,false>(bufA, bufB, 64, 256, 1, 1, W0, b0);  __syncthreads(); // 256x2x2
    dlayer<false,false>(bufB, bufA, 256, 128, 2, 2, W1, b1); __syncthreads(); // 128x4x4
    dlayer<false,false>(bufA, bufB, 128, 64, 4, 4, W2, b2);  __syncthreads(); // 64x8x8
    dlayer<false,false>(bufB, bufA, 64, 32, 8, 8, W3, b3);   __syncthreads(); // 32x16x16
    dlayer<false,false>(bufA, bufB, 32, 16, 16, 16, W4, b4); __syncthreads(); // 16x32x32
    dlayer<true,true>(bufB, g_decoded + (size_t)m * CPAD * DS * DS, 16, 3, 32, 32, W5, b5);
}

// ---------------------------------------------------------------------------
// Kernel 2: fused STN + depth-ordered first-nonzero compositing, 16x16 tiles
// with per-tile object culling (conservative; exact per-pixel test unchanged).
//   ix = fma(x, sx, ox):  sx = (32/w)*(2/IMG)
//                         ox = 31.5 + (32/w)*((1/IMG - 1) - (2cx - 1))
// ---------------------------------------------------------------------------
__global__ void __launch_bounds__(256) composite_kernel(
    const float* __restrict__ z_where,
    const int*   __restrict__ z_present,
    float* __restrict__ out)
{
    const int b = blockIdx.y;
    const int tx0 = (blockIdx.x % NTX) * TILE;
    const int ty0 = (blockIdx.x / NTX) * TILE;

    __shared__ float s_sx[TOPK], s_ox[TOPK], s_sy[TOPK], s_oy[TOPK];
    __shared__ int   s_flag[TOPK];
    __shared__ int   s_list[TOPK];
    __shared__ int   s_nc;

    const int tid = threadIdx.x;
    if (tid < TOPK) {
        const int ord = g_order[b * TOPK + tid];
        const float* zw = z_where + (size_t)(b * NPRI + ord) * 4;
        const float cx = zw[0], cy = zw[1];
        const float w = zw[2] + 1e-6f, h = zw[3] + 1e-6f;
        const float half = (float)DS * 0.5f;   // 32
        const float xsn = half / w;
        const float ysn = half / h;
        const float sx = xsn * (2.0f / (float)IMG);
        const float ox = half - 0.5f
                         + xsn * ((1.0f / (float)IMG - 1.0f) - (2.0f * cx - 1.0f));
        const float sy = ysn * (2.0f / (float)IMG);
        const float oy = half - 0.5f
                         + ysn * ((1.0f / (float)IMG - 1.0f) - (2.0f * cy - 1.0f));
        s_sx[tid] = sx; s_ox[tid] = ox; s_sy[tid] = sy; s_oy[tid] = oy;
        // conservative tile overlap: sampled iff ix in [-1, 64); sx,sy > 0
        const float ix_lo = fmaf((float)tx0, sx, ox);
        const float ix_hi = fmaf((float)(tx0 + TILE - 1), sx, ox);
        const float iy_lo = fmaf((float)ty0, sy, oy);
        const float iy_hi = fmaf((float)(ty0 + TILE - 1), sy, oy);
        const bool pres = (z_present[b * NPRI + ord] == 1);
        s_flag[tid] = (pres &&
                       ix_hi >= -1.01f && ix_lo < 64.01f &&
                       iy_hi >= -1.01f && iy_lo < 64.01f) ? 1 : 0;
    }
    __syncthreads();
    if (tid == 0) {
        int nc = 0;
        #pragma unroll
        for (int k = 0; k < TOPK; k++)
            if (s_flag[k]) s_list[nc++] = k;   // preserves depth order
        s_nc = nc;
    }
    __syncthreads();

    const int x = tx0 + (tid % TILE);
    const int y = ty0 + (tid / TILE);
    if (x >= IMG || y >= IMG) return;
    const float fx = (float)x, fy = (float)y;

    float r0 = 0.0f, r1 = 0.0f, r2 = 0.0f;
    int done = 0;
    const int nc = s_nc;

    for (int kk = 0; kk < nc; kk++) {
        const int k = s_list[kk];
        const float ix = fmaf(fx, s_sx[k], s_ox[k]);
        const float iy = fmaf(fy, s_sy[k], s_oy[k]);
        const float ix0f = floorf(ix), iy0f = floorf(iy);
        if (!(ix0f >= -1.0f && ix0f <= 63.0f && iy0f >= -1.0f && iy0f <= 63.0f))
            continue;   // sample exactly zero -> never "first"
        const float wx1 = ix - ix0f, wy1 = iy - iy0f;
        const float wx0 = 1.0f - wx1, wy0 = 1.0f - wy1;
        const int ix0 = (int)ix0f, iy0 = (int)iy0f;
        const bool vx0 = (ix0 >= 0), vx1 = (ix0 <= 62);
        const bool vy0 = (iy0 >= 0), vy1 = (iy0 <= 62);
        const float w00 = (vy0 && vx0) ? wy0 * wx0 : 0.0f;
        const float w01 = (vy0 && vx1) ? wy0 * wx1 : 0.0f;
        const float w10 = (vy1 && vx0) ? wy1 * wx0 : 0.0f;
        const float w11 = (vy1 && vx1) ? wy1 * wx1 : 0.0f;
        const int x0c = max(ix0, 0),     x1c = min(ix0 + 1, DS - 1);
        const int y0c = max(iy0, 0),     y1c = min(iy0 + 1, DS - 1);
        const int i00 = y0c * DS + x0c, i01 = y0c * DS + x1c;
        const int i10 = y1c * DS + x0c, i11 = y1c * DS + x1c;
        const float4* __restrict__ base = reinterpret_cast<const float4*>(g_decoded)
                                          + (size_t)(b * TOPK + k) * DS * DS;
        const float4 t00 = __ldg(base + i00);
        const float4 t01 = __ldg(base + i01);
        const float4 t10 = __ldg(base + i10);
        const float4 t11 = __ldg(base + i11);

        const float s0 = t00.x * w00 + t01.x * w01 + t10.x * w10 + t11.x * w11;
        const float s1 = t00.y * w00 + t01.y * w01 + t10.y * w10 + t11.y * w11;
        const float s2 = t00.z * w00 + t01.z * w01 + t10.z * w10 + t11.z * w11;

        if (!(done & 1) && s0 != 0.0f) { r0 = s0; done |= 1; }
        if (!(done & 2) && s1 != 0.0f) { r1 = s1; done |= 2; }
        if (!(done & 4) && s2 != 0.0f) { r2 = s2; done |= 4; }
        if (done == 7) break;
    }

    const size_t pix = (size_t)y * IMG + x;
    out[((size_t)(b * 3 + 0) * IMG * IMG) + pix] = r0;
    out[((size_t)(b * 3 + 1) * IMG * IMG) + pix] = r1;
    out[((size_t)(b * 3 + 2) * IMG * IMG) + pix] = r2;
}

// ---------------------------------------------------------------------------
extern "C" void kernel_launch(void* const* d_in, const int* in_sizes, int n_in,
                              void* d_out, int out_size)
{
    const float* z_what    = (const float*)d_in[0];
    const float* z_where   = (const float*)d_in[1];
    const int*   z_present = (const int*)  d_in[2];
    const float* z_depth   = (const float*)d_in[3];
    const float* W0 = (const float*)d_in[4];  const float* b0 = (const float*)d_in[5];
    const float* W1 = (const float*)d_in[6];  const float* b1 = (const float*)d_in[7];
    const float* W2 = (const float*)d_in[8];  const float* b2 = (const float*)d_in[9];
    const float* W3 = (const float*)d_in[10]; const float* b3 = (const float*)d_in[11];
    const float* W4 = (const float*)d_in[12]; const float* b4 = (const float*)d_in[13];
    const float* W5 = (const float*)d_in[14]; const float* b5 = (const float*)d_in[15];
    float* out = (float*)d_out;

    static bool attr_set = false;
    if (!attr_set) {
        cudaFuncSetAttribute(decode_kernel,
                             cudaFuncAttributeMaxDynamicSharedMemorySize,
                             (8192 + 16384) * sizeof(float));
        attr_set = true;
    }

    decode_kernel<<<NOBJ, 256, (8192 + 16384) * sizeof(float)>>>(
        z_depth, z_what, W0, b0, W1, b1, W2, b2, W3, b3, W4, b4, W5, b5);

    dim3 cgrid(NTX * NTX, BATCH);
    composite_kernel<<<cgrid, 256>>>(z_where, z_present, out);
}

// round 6
// speedup vs baseline: 3.5936x; 2.1392x over previous
#include <cuda_runtime.h>
#include <math.h>

#define NLOC 1940
#define NPRI 8732
#define BATCH 16
#define TOPK 10
#define NOBJ (BATCH*TOPK)
#define DS 64          // decoded image size
#define IMG 300
#define ZWHAT 64
#define CPAD 4         // padded channel count (3 used + 1 pad) -> 16B/pixel
#define TILE 16        // composite tile edge
#define NTX ((IMG + TILE - 1) / TILE)   // 19

// scratch (device globals; no allocation allowed)
__device__ float g_decoded[NOBJ * CPAD * DS * DS];   // [obj][pix][4], 10.5 MB
__device__ int   g_order[BATCH * TOPK];

// ---------------------------------------------------------------------------
// f32x2 packed-math helpers (sm_103a FFMA2 path; ptxas won't auto-fuse)
// ---------------------------------------------------------------------------
__device__ __forceinline__ unsigned long long pack2(float lo, float hi) {
    unsigned long long r;
    asm("mov.b64 %0, {%1, %2};" : "=l"(r) : "f"(lo), "f"(hi));
    return r;
}
__device__ __forceinline__ void unpack2(unsigned long long v, float& a, float& b) {
    asm("mov.b64 {%0, %1}, %2;" : "=f"(a), "=f"(b) : "l"(v));
}
__device__ __forceinline__ unsigned long long ffma2(unsigned long long a,
                                                    unsigned long long b,
                                                    unsigned long long c) {
    unsigned long long d;
    asm("fma.rn.f32x2 %0, %1, %2, %3;" : "=l"(d) : "l"(a), "l"(b), "l"(c));
    return d;
}

// prior index -> location index (closed form of _recon_indices)
__device__ __forceinline__ int prior_to_loc(int i) {
    if (i < 5776) return i >> 2;
    if (i < 7942) return 1444 + (i - 5776) / 6;
    if (i < 8542) return 1805 + (i - 7942) / 6;
    if (i < 8692) return 1905 + (i - 8542) / 6;
    if (i < 8728) return 1930 + ((i - 8692) >> 2);
    return 1939;
}
__device__ __forceinline__ void loc_to_priors(int l, int& start, int& bpl) {
    if (l < 1444)      { start = 4 * l;                 bpl = 4; }
    else if (l < 1805) { start = 5776 + 6 * (l - 1444); bpl = 6; }
    else if (l < 1905) { start = 7942 + 6 * (l - 1805); bpl = 6; }
    else if (l < 1930) { start = 8542 + 6 * (l - 1905); bpl = 6; }
    else               { start = 8692 + 4 * (l - 1930); bpl = 4; }
}
__device__ __forceinline__ bool better(float a, int ia, float b, int ib) {
    return a > b || (a == b && ia < ib);
}
__device__ __forceinline__ void insert3(float v, int i,
                                        float& v0, int& i0, float& v1, int& i1,
                                        float& v2, int& i2) {
    if (better(v, i, v0, i0)) { v2 = v1; i2 = i1; v1 = v0; i1 = i0; v0 = v; i0 = i; }
    else if (better(v, i, v1, i1)) { v2 = v1; i2 = i1; v1 = v; i1 = i; }
    else if (better(v, i, v2, i2)) { v2 = v; i2 = i; }
}

// block-redundant top-3 locations of batch b; returns prior index of rank j.
__device__ __forceinline__ int block_topk(const float* __restrict__ z_depth,
                                          int b, int j, float* scratch) {
    const int tid = threadIdx.x;
    float (*sv)[3] = (float(*)[3])scratch;
    int   (*si)[3] = (int(*)[3])(scratch + 256 * 3);

    float v0 = -INFINITY, v1 = -INFINITY, v2 = -INFINITY;
    int   i0 = 0x7fffffff, i1 = 0x7fffffff, i2 = 0x7fffffff;
    const float4* __restrict__ zd4 =
        reinterpret_cast<const float4*>(z_depth + b * NLOC);
    for (int i = tid; i < NLOC / 4; i += 256) {
        const float4 v = __ldg(zd4 + i);
        insert3(v.x, 4 * i + 0, v0, i0, v1, i1, v2, i2);
        insert3(v.y, 4 * i + 1, v0, i0, v1, i1, v2, i2);
        insert3(v.z, 4 * i + 2, v0, i0, v1, i1, v2, i2);
        insert3(v.w, 4 * i + 3, v0, i0, v1, i1, v2, i2);
    }
    sv[tid][0] = v0; sv[tid][1] = v1; sv[tid][2] = v2;
    si[tid][0] = i0; si[tid][1] = i1; si[tid][2] = i2;
    __syncthreads();
    for (int s = 128; s > 0; s >>= 1) {
        if (tid < s) {
            #pragma unroll
            for (int q = 0; q < 3; q++)
                insert3(sv[tid + s][q], si[tid + s][q], v0, i0, v1, i1, v2, i2);
            sv[tid][0] = v0; sv[tid][1] = v1; sv[tid][2] = v2;
            si[tid][0] = i0; si[tid][1] = i1; si[tid][2] = i2;
        }
        __syncthreads();
    }
    __shared__ int s_ord;
    if (tid == 0) {
        int ranks[3] = { i0, i1, i2 };
        int ord = -1, cnt = 0;
        #pragma unroll
        for (int r = 0; r < 3; r++) {
            int start, bpl;
            loc_to_priors(ranks[r], start, bpl);
            if (ord < 0 && j < cnt + bpl) ord = start + (j - cnt);
            cnt += bpl;
        }
        s_ord = ord;
    }
    __syncthreads();
    return s_ord;
}

// ---------------------------------------------------------------------------
// Register-tiled deconv layer. Thread owns (o = t%CO, row y = t/CO): all W
// pixels of that row. Weight float4 loaded once per c, reused across the row
// via packed f32x2 FMAs over pixel pairs. Requires CO*H == 256.
// deconv2x2 stride 2: out[o,2y+a,2x+b] = bias[o] + sum_c in[c,y,x]*W[c,o,a,b]
// ---------------------------------------------------------------------------
template<int CI, int CO, int H, int W>
__device__ __forceinline__ void dlayer_t(const float* __restrict__ in,
                                         float* __restrict__ out,
                                         const float* __restrict__ Wt,
                                         const float* __restrict__ bias)
{
    static_assert(CO * H == 256, "thread mapping");
    constexpr int HW = H * W;
    const int o = threadIdx.x % CO;
    const int y = threadIdx.x / CO;
    const float4* __restrict__ W4 = reinterpret_cast<const float4*>(Wt);
    const float bo = __ldg(bias + o);
    float* orow0 = out + (o * 2 * H + 2 * y) * (2 * W);
    float* orow1 = orow0 + 2 * W;

    if constexpr (W == 1) {
        float a0 = bo, a1 = bo, a2 = bo, a3 = bo;
        #pragma unroll 8
        for (int c = 0; c < CI; c++) {
            const float iv = in[c];
            const float4 wv = __ldg(W4 + c * CO + o);
            a0 = fmaf(iv, wv.x, a0);
            a1 = fmaf(iv, wv.y, a1);
            a2 = fmaf(iv, wv.z, a2);
            a3 = fmaf(iv, wv.w, a3);
        }
        orow0[0] = fmaxf(a0, 0.f); orow0[1] = fmaxf(a1, 0.f);
        orow1[0] = fmaxf(a2, 0.f); orow1[1] = fmaxf(a3, 0.f);
    } else {
        constexpr int NP = W / 2;   // pixel pairs in the row
        unsigned long long acc[4][NP];
        const unsigned long long bb = pack2(bo, bo);
        #pragma unroll
        for (int q = 0; q < 4; q++)
            #pragma unroll
            for (int pp = 0; pp < NP; pp++) acc[q][pp] = bb;

        const float* iprow = in + y * W;
        #pragma unroll 4
        for (int c = 0; c < CI; c++) {
            const float4 wv = __ldg(W4 + c * CO + o);
            const unsigned long long w0 = pack2(wv.x, wv.x);
            const unsigned long long w1 = pack2(wv.y, wv.y);
            const unsigned long long w2 = pack2(wv.z, wv.z);
            const unsigned long long w3 = pack2(wv.w, wv.w);
            const unsigned long long* iv2 =
                reinterpret_cast<const unsigned long long*>(iprow + c * HW);
            #pragma unroll
            for (int pp = 0; pp < NP; pp++) {
                const unsigned long long iv = iv2[pp];
                acc[0][pp] = ffma2(iv, w0, acc[0][pp]);
                acc[1][pp] = ffma2(iv, w1, acc[1][pp]);
                acc[2][pp] = ffma2(iv, w2, acc[2][pp]);
                acc[3][pp] = ffma2(iv, w3, acc[3][pp]);
            }
        }
        #pragma unroll
        for (int pp = 0; pp < NP; pp++) {
            float a0l, a0h, a1l, a1h, a2l, a2h, a3l, a3h;
            unpack2(acc[0][pp], a0l, a0h); unpack2(acc[1][pp], a1l, a1h);
            unpack2(acc[2][pp], a2l, a2h); unpack2(acc[3][pp], a3l, a3h);
            const float4 r0 = make_float4(fmaxf(a0l, 0.f), fmaxf(a1l, 0.f),
                                          fmaxf(a0h, 0.f), fmaxf(a1h, 0.f));
            const float4 r1 = make_float4(fmaxf(a2l, 0.f), fmaxf(a3l, 0.f),
                                          fmaxf(a2h, 0.f), fmaxf(a3h, 0.f));
            *reinterpret_cast<float4*>(orow0 + 4 * pp) = r0;
            *reinterpret_cast<float4*>(orow1 + 4 * pp) = r1;
        }
    }
}

// Final layer: ci=16, co=3, 32x32 -> 64x64, sigmoid, CPAD-interleaved output.
// Thread owns 4 src pixels (all 3 channels) -> 16 float4 texel stores.
// sw: 195 floats staged in smem: W5 (192) + b5 (3).
__device__ __forceinline__ void final_layer(const float* __restrict__ in,
                                            const float* __restrict__ sw,
                                            float* __restrict__ gout)
{
    const int tid = threadIdx.x;
    const int pbase = tid * 4;
    const int sy = pbase >> 5;      // src row in 32x32
    const int sx = pbase & 31;      // src col (multiple of 4)

    unsigned long long acc[3][4][2];
    #pragma unroll
    for (int o = 0; o < 3; o++) {
        const unsigned long long bb = pack2(sw[192 + o], sw[192 + o]);
        #pragma unroll
        for (int q = 0; q < 4; q++) { acc[o][q][0] = bb; acc[o][q][1] = bb; }
    }

    #pragma unroll 4
    for (int c = 0; c < 16; c++) {
        const unsigned long long* iv2 =
            reinterpret_cast<const unsigned long long*>(in + c * 1024 + pbase);
        const unsigned long long i0 = iv2[0], i1 = iv2[1];
        #pragma unroll
        for (int o = 0; o < 3; o++) {
            const float4 wv = *reinterpret_cast<const float4*>(sw + (c * 3 + o) * 4);
            const unsigned long long w0 = pack2(wv.x, wv.x);
            const unsigned long long w1 = pack2(wv.y, wv.y);
            const unsigned long long w2 = pack2(wv.z, wv.z);
            const unsigned long long w3 = pack2(wv.w, wv.w);
            acc[o][0][0] = ffma2(i0, w0, acc[o][0][0]);
            acc[o][0][1] = ffma2(i1, w0, acc[o][0][1]);
            acc[o][1][0] = ffma2(i0, w1, acc[o][1][0]);
            acc[o][1][1] = ffma2(i1, w1, acc[o][1][1]);
            acc[o][2][0] = ffma2(i0, w2, acc[o][2][0]);
            acc[o][2][1] = ffma2(i1, w2, acc[o][2][1]);
            acc[o][3][0] = ffma2(i0, w3, acc[o][3][0]);
            acc[o][3][1] = ffma2(i1, w3, acc[o][3][1]);
        }
    }

    float4* g4 = reinterpret_cast<float4*>(gout);
    #pragma unroll
    for (int pp = 0; pp < 2; pp++) {
        #pragma unroll
        for (int e = 0; e < 2; e++) {
            const int px = sx + 2 * pp + e;
            #pragma unroll
            for (int q = 0; q < 4; q++) {
                float r[3];
                #pragma unroll
                for (int o = 0; o < 3; o++) {
                    float a, bv; unpack2(acc[o][q][pp], a, bv);
                    const float v = e ? bv : a;
                    r[o] = 1.0f / (1.0f + __expf(-v));
                }
                const int qa = q >> 1, qb = q & 1;
                g4[(2 * sy + qa) * DS + 2 * px + qb] = make_float4(r[0], r[1], r[2], 0.0f);
            }
        }
    }
}

// ---------------------------------------------------------------------------
// Kernel 1: decode 160 objects (block = object). Redundant per-block top-3.
// ---------------------------------------------------------------------------
__global__ void __launch_bounds__(256, 2) decode_kernel(
    const float* __restrict__ z_depth,
    const float* __restrict__ z_what,
    const float* __restrict__ W0, const float* __restrict__ b0,
    const float* __restrict__ W1, const float* __restrict__ b1,
    const float* __restrict__ W2, const float* __restrict__ b2,
    const float* __restrict__ W3, const float* __restrict__ b3,
    const float* __restrict__ W4, const float* __restrict__ b4,
    const float* __restrict__ W5, const float* __restrict__ b5)
{
    extern __shared__ float sm[];
    float* bufA = sm;           // up to 8192 floats
    float* bufB = sm + 8192;    // up to 16384 floats

    const int m = blockIdx.x;
    const int b = m / TOPK;
    const int j = m % TOPK;

    const int ord = block_topk(z_depth, b, j, bufB);
    if (threadIdx.x == 0) g_order[m] = ord;

    const int loc = prior_to_loc(ord);
    const float* src = z_what + (size_t)(b * NLOC + loc) * ZWHAT;
    if (threadIdx.x < ZWHAT) bufA[threadIdx.x] = src[threadIdx.x];
    __syncthreads();

    dlayer_t< 64, 256,  1,  1>(bufA, bufB, W0, b0); __syncthreads(); // 256x2x2
    dlayer_t<256, 128,  2,  2>(bufB, bufA, W1, b1); __syncthreads(); // 128x4x4
    dlayer_t<128,  64,  4,  4>(bufA, bufB, W2, b2); __syncthreads(); // 64x8x8
    dlayer_t< 64,  32,  8,  8>(bufB, bufA, W3, b3); __syncthreads(); // 32x16x16
    dlayer_t< 32,  16, 16, 16>(bufA, bufB, W4, b4); __syncthreads(); // 16x32x32

    // stage W5 + b5 into (now free) bufA, then final layer bufB -> global
    if (threadIdx.x < 192) bufA[threadIdx.x] = W5[threadIdx.x];
    if (threadIdx.x < 3)   bufA[192 + threadIdx.x] = b5[threadIdx.x];
    __syncthreads();
    final_layer(bufB, bufA, g_decoded + (size_t)m * CPAD * DS * DS);
}

// ---------------------------------------------------------------------------
// Kernel 2: fused STN + depth-ordered first-nonzero compositing, 16x16 tiles
// with conservative per-tile object culling (exact per-pixel test unchanged).
// ---------------------------------------------------------------------------
__global__ void __launch_bounds__(256) composite_kernel(
    const float* __restrict__ z_where,
    const int*   __restrict__ z_present,
    float* __restrict__ out)
{
    const int b = blockIdx.y;
    const int tx0 = (blockIdx.x % NTX) * TILE;
    const int ty0 = (blockIdx.x / NTX) * TILE;

    __shared__ float s_sx[TOPK], s_ox[TOPK], s_sy[TOPK], s_oy[TOPK];
    __shared__ int   s_flag[TOPK];
    __shared__ int   s_list[TOPK];
    __shared__ int   s_nc;

    const int tid = threadIdx.x;
    if (tid < TOPK) {
        const int ord = g_order[b * TOPK + tid];
        const float* zw = z_where + (size_t)(b * NPRI + ord) * 4;
        const float cx = zw[0], cy = zw[1];
        const float w = zw[2] + 1e-6f, h = zw[3] + 1e-6f;
        const float half = (float)DS * 0.5f;   // 32
        const float xsn = half / w;
        const float ysn = half / h;
        const float sx = xsn * (2.0f / (float)IMG);
        const float ox = half - 0.5f
                         + xsn * ((1.0f / (float)IMG - 1.0f) - (2.0f * cx - 1.0f));
        const float sy = ysn * (2.0f / (float)IMG);
        const float oy = half - 0.5f
                         + ysn * ((1.0f / (float)IMG - 1.0f) - (2.0f * cy - 1.0f));
        s_sx[tid] = sx; s_ox[tid] = ox; s_sy[tid] = sy; s_oy[tid] = oy;
        const float ix_lo = fmaf((float)tx0, sx, ox);
        const float ix_hi = fmaf((float)(tx0 + TILE - 1), sx, ox);
        const float iy_lo = fmaf((float)ty0, sy, oy);
        const float iy_hi = fmaf((float)(ty0 + TILE - 1), sy, oy);
        const bool pres = (z_present[b * NPRI + ord] == 1);
        s_flag[tid] = (pres &&
                       ix_hi >= -1.01f && ix_lo < 64.01f &&
                       iy_hi >= -1.01f && iy_lo < 64.01f) ? 1 : 0;
    }
    __syncthreads();
    if (tid == 0) {
        int nc = 0;
        #pragma unroll
        for (int k = 0; k < TOPK; k++)
            if (s_flag[k]) s_list[nc++] = k;   // preserves depth order
        s_nc = nc;
    }
    __syncthreads();

    const int x = tx0 + (tid % TILE);
    const int y = ty0 + (tid / TILE);
    if (x >= IMG || y >= IMG) return;
    const float fx = (float)x, fy = (float)y;

    float r0 = 0.0f, r1 = 0.0f, r2 = 0.0f;
    int done = 0;
    const int nc = s_nc;

    for (int kk = 0; kk < nc; kk++) {
        const int k = s_list[kk];
        const float ix = fmaf(fx, s_sx[k], s_ox[k]);
        const float iy = fmaf(fy, s_sy[k], s_oy[k]);
        const float ix0f = floorf(ix), iy0f = floorf(iy);
        if (!(ix0f >= -1.0f && ix0f <= 63.0f && iy0f >= -1.0f && iy0f <= 63.0f))
            continue;   // sample exactly zero -> never "first"
        const float wx1 = ix - ix0f, wy1 = iy - iy0f;
        const float wx0 = 1.0f - wx1, wy0 = 1.0f - wy1;
        const int ix0 = (int)ix0f, iy0 = (int)iy0f;
        const bool vx0 = (ix0 >= 0), vx1 = (ix0 <= 62);
        const bool vy0 = (iy0 >= 0), vy1 = (iy0 <= 62);
        const float w00 = (vy0 && vx0) ? wy0 * wx0 : 0.0f;
        const float w01 = (vy0 && vx1) ? wy0 * wx1 : 0.0f;
        const float w10 = (vy1 && vx0) ? wy1 * wx0 : 0.0f;
        const float w11 = (vy1 && vx1) ? wy1 * wx1 : 0.0f;
        const int x0c = max(ix0, 0),     x1c = min(ix0 + 1, DS - 1);
        const int y0c = max(iy0, 0),     y1c = min(iy0 + 1, DS - 1);
        const int i00 = y0c * DS + x0c, i01 = y0c * DS + x1c;
        const int i10 = y1c * DS + x0c, i11 = y1c * DS + x1c;
        const float4* __restrict__ base = reinterpret_cast<const float4*>(g_decoded)
                                          + (size_t)(b * TOPK + k) * DS * DS;
        const float4 t00 = __ldg(base + i00);
        const float4 t01 = __ldg(base + i01);
        const float4 t10 = __ldg(base + i10);
        const float4 t11 = __ldg(base + i11);

        const float s0 = t00.x * w00 + t01.x * w01 + t10.x * w10 + t11.x * w11;
        const float s1 = t00.y * w00 + t01.y * w01 + t10.y * w10 + t11.y * w11;
        const float s2 = t00.z * w00 + t01.z * w01 + t10.z * w10 + t11.z * w11;

        if (!(done & 1) && s0 != 0.0f) { r0 = s0; done |= 1; }
        if (!(done & 2) && s1 != 0.0f) { r1 = s1; done |= 2; }
        if (!(done & 4) && s2 != 0.0f) { r2 = s2; done |= 4; }
        if (done == 7) break;
    }

    const size_t pix = (size_t)y * IMG + x;
    out[((size_t)(b * 3 + 0) * IMG * IMG) + pix] = r0;
    out[((size_t)(b * 3 + 1) * IMG * IMG) + pix] = r1;
    out[((size_t)(b * 3 + 2) * IMG * IMG) + pix] = r2;
}

// ---------------------------------------------------------------------------
extern "C" void kernel_launch(void* const* d_in, const int* in_sizes, int n_in,
                              void* d_out, int out_size)
{
    const float* z_what    = (const float*)d_in[0];
    const float* z_where   = (const float*)d_in[1];
    const int*   z_present = (const int*)  d_in[2];
    const float* z_depth   = (const float*)d_in[3];
    const float* W0 = (const float*)d_in[4];  const float* b0 = (const float*)d_in[5];
    const float* W1 = (const float*)d_in[6];  const float* b1 = (const float*)d_in[7];
    const float* W2 = (const float*)d_in[8];  const float* b2 = (const float*)d_in[9];
    const float* W3 = (const float*)d_in[10]; const float* b3 = (const float*)d_in[11];
    const float* W4 = (const float*)d_in[12]; const float* b4 = (const float*)d_in[13];
    const float* W5 = (const float*)d_in[14]; const float* b5 = (const float*)d_in[15];
    float* out = (float*)d_out;

    static bool attr_set = false;
    if (!attr_set) {
        cudaFuncSetAttribute(decode_kernel,
                             cudaFuncAttributeMaxDynamicSharedMemorySize,
                             (8192 + 16384) * sizeof(float));
        attr_set = true;
    }

    decode_kernel<<<NOBJ, 256, (8192 + 16384) * sizeof(float)>>>(
        z_depth, z_what, W0, b0, W1, b1, W2, b2, W3, b3, W4, b4, W5, b5);

    dim3 cgrid(NTX * NTX, BATCH);
    composite_kernel<<<cgrid, 256>>>(z_where, z_present, out);
}